// round 1
// baseline (speedup 1.0000x reference)
#include <cuda_runtime.h>
#include <cuda_bf16.h>
#include <math.h>
#include <stdint.h>

// ----------------------------------------------------------------------------
// Problem constants
// ----------------------------------------------------------------------------
#define B      2
#define N_SEQ  2048
#define DIM    2048
#define HEADS  16
#define DHEAD  128
#define INNER  (HEADS * DHEAD)       // 2048
#define ROWS   (B * N_SEQ)           // 4096

// ----------------------------------------------------------------------------
// Scratch (device globals; no allocations allowed)
// ----------------------------------------------------------------------------
__device__ float g_xn[ROWS * DIM];          // normalized input    [4096, 2048]
__device__ float g_q [ROWS * INNER];        // q projection        [4096, 2048]
__device__ float g_kv[ROWS * 2 * INNER];    // kv projection       [4096, 4096]
__device__ float g_o [ROWS * INNER];        // attention output    [4096, 2048]

// ----------------------------------------------------------------------------
// RMSNorm:  xn = x / max(rms(x), 1e-8) * g
// ----------------------------------------------------------------------------
__global__ __launch_bounds__(256) void rmsnorm_kernel(
    const float* __restrict__ x, const float* __restrict__ g,
    float* __restrict__ xn)
{
    const int row = blockIdx.x;
    const float* xr = x  + (size_t)row * DIM;
    float*       xo = xn + (size_t)row * DIM;

    float ss = 0.f;
    for (int i = threadIdx.x; i < DIM; i += 256) {
        float v = xr[i];
        ss += v * v;
    }
    __shared__ float red[8];
    #pragma unroll
    for (int o = 16; o > 0; o >>= 1) ss += __shfl_xor_sync(0xffffffffu, ss, o);
    if ((threadIdx.x & 31) == 0) red[threadIdx.x >> 5] = ss;
    __syncthreads();
    if (threadIdx.x < 8) {
        float v = red[threadIdx.x];
        #pragma unroll
        for (int o = 4; o > 0; o >>= 1) v += __shfl_xor_sync(0x000000ffu, v, o);
        if (threadIdx.x == 0) red[0] = v;
    }
    __syncthreads();
    const float rms = sqrtf(red[0] * (1.f / (float)DIM));
    const float inv = 1.f / fmaxf(rms, 1e-8f);
    for (int i = threadIdx.x; i < DIM; i += 256)
        xo[i] = xr[i] * inv * g[i];
}

// ----------------------------------------------------------------------------
// SGEMM: C[M,N] = A[M,K] @ B[K,N]   (all row-major, dims divisible by tiles)
// BM=128 BN=128 BK=8, 256 threads, 8x8 register microtile.
// ----------------------------------------------------------------------------
#define GBM 128
#define GBN 128
#define GBK 8
#define GTM 8
#define GTN 8

__global__ __launch_bounds__(256) void sgemm_kernel(
    int M, int N, int K,
    const float* __restrict__ A, const float* __restrict__ Bm,
    float* __restrict__ C)
{
    __shared__ float As[GBK][GBM];
    __shared__ float Bs[GBK][GBN];

    const int tid = threadIdx.x;
    const int threadCol = tid % (GBN / GTN);  // 0..15
    const int threadRow = tid / (GBN / GTN);  // 0..15

    const int innerRowA = tid >> 1;           // 0..127
    const int innerColA = (tid & 1) * 4;      // 0 or 4
    const int innerRowB = tid >> 5;           // 0..7
    const int innerColB = (tid & 31) * 4;     // 0..124

    const float* Ap = A  + (size_t)blockIdx.y * GBM * K;
    const float* Bp = Bm + (size_t)blockIdx.x * GBN;
    float*       Cp = C  + (size_t)blockIdx.y * GBM * N + (size_t)blockIdx.x * GBN;

    float acc[GTM][GTN] = {};
    float regM[GTM], regN[GTN];

    for (int k0 = 0; k0 < K; k0 += GBK) {
        float4 a = *(const float4*)(Ap + (size_t)innerRowA * K + innerColA);
        As[innerColA + 0][innerRowA] = a.x;
        As[innerColA + 1][innerRowA] = a.y;
        As[innerColA + 2][innerRowA] = a.z;
        As[innerColA + 3][innerRowA] = a.w;
        *(float4*)(&Bs[innerRowB][innerColB]) =
            *(const float4*)(Bp + (size_t)innerRowB * N + innerColB);
        __syncthreads();
        Ap += GBK;
        Bp += (size_t)GBK * N;
        #pragma unroll
        for (int k = 0; k < GBK; k++) {
            #pragma unroll
            for (int i = 0; i < GTM; i++) regM[i] = As[k][threadRow * GTM + i];
            #pragma unroll
            for (int j = 0; j < GTN; j++) regN[j] = Bs[k][threadCol * GTN + j];
            #pragma unroll
            for (int i = 0; i < GTM; i++)
                #pragma unroll
                for (int j = 0; j < GTN; j++)
                    acc[i][j] += regM[i] * regN[j];
        }
        __syncthreads();
    }

    #pragma unroll
    for (int i = 0; i < GTM; i++) {
        #pragma unroll
        for (int j = 0; j < GTN; j += 4) {
            float4 v = make_float4(acc[i][j], acc[i][j+1], acc[i][j+2], acc[i][j+3]);
            *(float4*)(Cp + (size_t)(threadRow * GTM + i) * N + threadCol * GTN + j) = v;
        }
    }
}

// ----------------------------------------------------------------------------
// RoPE (in place). Buffer is [ROWS, ncols]; heads live at col0 + h*DHEAD.
//   out[d]    = t[d]   *cos(p[d])    - t[d+64]*sin(p[d])      (d < 64)
//   out[d+64] = t[d+64]*cos(p[d+64]) + t[d]   *sin(p[d+64])
// ----------------------------------------------------------------------------
__global__ __launch_bounds__(256) void rope_kernel(
    float* __restrict__ t, const float* __restrict__ re, int ncols)
{
    const size_t total = (size_t)ROWS * HEADS * 64;
    size_t idx = (size_t)blockIdx.x * blockDim.x + threadIdx.x;
    if (idx >= total) return;
    const int d = (int)(idx & 63);
    const int h = (int)((idx >> 6) & (HEADS - 1));
    const int r = (int)(idx >> 10);
    const int n = r & (N_SEQ - 1);

    float* base = t + (size_t)r * ncols + h * DHEAD;
    const float p1 = re[n * DHEAD + d];
    const float p2 = re[n * DHEAD + d + 64];
    const float t1 = base[d];
    const float t2 = base[d + 64];
    base[d]      = t1 * cosf(p1) - t2 * sinf(p1);
    base[d + 64] = t2 * cosf(p2) + t1 * sinf(p2);
}

// ----------------------------------------------------------------------------
// Causal flash attention, fp32.
//   grid = (qtiles=32, b*h=32), 256 threads.
//   4 lanes per query row; lane `part` owns d-indices {4*i + part}.
//   BLOCK_M=64 queries, BLOCK_N=32 keys per tile.
// ----------------------------------------------------------------------------
#define AT_BM 64
#define AT_BN 32

__global__ __launch_bounds__(256) void attn_kernel(
    const float* __restrict__ Q, const float* __restrict__ KV,
    float* __restrict__ O)
{
    const int bh = blockIdx.y;
    const int b  = bh >> 4;
    const int h  = bh & 15;
    const int qt = blockIdx.x;

    const int tid  = threadIdx.x;
    const int row  = tid >> 2;     // 0..63
    const int part = tid & 3;      // 0..3
    const int qrow = qt * AT_BM + row;   // global query position n

    __shared__ float Ks[AT_BN][DHEAD];
    __shared__ float Vs[AT_BN][DHEAD];

    // Q fragment: d indices 4*i + part
    const float* qptr = Q + ((size_t)(b * N_SEQ + qrow)) * INNER + h * DHEAD;
    float qreg[32];
    #pragma unroll
    for (int i = 0; i < 32; i++) qreg[i] = qptr[4 * i + part];

    float oacc[32] = {};
    float m = -INFINITY, l = 0.f;
    const float scale = 0.088388347648318447f;  // 128^-0.5
    const int lanebase = (tid & 31) & ~3;       // lane of part 0 for this row

    const int ntiles = 2 * qt + 2;              // keys [0, qt*64+64)
    for (int kt = 0; kt < ntiles; kt++) {
        __syncthreads();
        // cooperative load of K,V tile: 32 rows x 128 floats each
        for (int idx = tid; idx < AT_BN * 32; idx += 256) {
            const int j  = idx >> 5;
            const int dd = (idx & 31) * 4;
            const size_t gro = ((size_t)(b * N_SEQ + kt * AT_BN + j)) * (2 * INNER);
            *(float4*)&Ks[j][dd] = *(const float4*)(KV + gro + h * DHEAD + dd);
            *(float4*)&Vs[j][dd] = *(const float4*)(KV + gro + INNER + h * DHEAD + dd);
        }
        __syncthreads();

        // scores for this tile
        float pbuf[8];
        float tmax = -INFINITY;
        #pragma unroll 1
        for (int j = 0; j < AT_BN; j++) {
            float s = 0.f;
            #pragma unroll
            for (int i = 0; i < 32; i++) s += qreg[i] * Ks[j][4 * i + part];
            s += __shfl_xor_sync(0xffffffffu, s, 1);
            s += __shfl_xor_sync(0xffffffffu, s, 2);
            s *= scale;
            const int jg = kt * AT_BN + j;
            if (jg > qrow) s = -INFINITY;
            if ((j >> 3) == part) pbuf[j & 7] = s;
            tmax = fmaxf(tmax, s);
        }

        // online softmax update
        const float mnew = fmaxf(m, tmax);
        const float corr = __expf(m - mnew);
        l *= corr;
        #pragma unroll
        for (int i = 0; i < 32; i++) oacc[i] *= corr;
        float psum = 0.f;
        #pragma unroll
        for (int jj = 0; jj < 8; jj++) {
            pbuf[jj] = __expf(pbuf[jj] - mnew);
            psum += pbuf[jj];
        }
        psum += __shfl_xor_sync(0xffffffffu, psum, 1);
        psum += __shfl_xor_sync(0xffffffffu, psum, 2);
        l += psum;
        m = mnew;

        // O += P @ V
        #pragma unroll 1
        for (int j = 0; j < AT_BN; j++) {
            const float p = __shfl_sync(0xffffffffu, pbuf[j & 7], lanebase + (j >> 3));
            #pragma unroll
            for (int i = 0; i < 32; i++) oacc[i] += p * Vs[j][4 * i + part];
        }
    }

    const float inv = 1.f / l;
    float* optr = O + ((size_t)(b * N_SEQ + qrow)) * INNER + h * DHEAD;
    #pragma unroll
    for (int i = 0; i < 32; i++) optr[4 * i + part] = oacc[i] * inv;
}

// ----------------------------------------------------------------------------
// Launch
// ----------------------------------------------------------------------------
extern "C" void kernel_launch(void* const* d_in, const int* in_sizes, int n_in,
                              void* d_out, int out_size)
{
    const float* x   = (const float*)d_in[0];
    const float* re  = (const float*)d_in[1];
    const float* g   = (const float*)d_in[2];
    const float* Wq  = (const float*)d_in[3];
    const float* Wkv = (const float*)d_in[4];
    const float* Wo  = (const float*)d_in[5];
    float* out = (float*)d_out;

    float *xn, *q, *kv, *o;
    cudaGetSymbolAddress((void**)&xn, g_xn);
    cudaGetSymbolAddress((void**)&q,  g_q);
    cudaGetSymbolAddress((void**)&kv, g_kv);
    cudaGetSymbolAddress((void**)&o,  g_o);

    // 1) RMSNorm
    rmsnorm_kernel<<<ROWS, 256>>>(x, g, xn);

    // 2) projections
    dim3 gq(INNER / GBN, ROWS / GBM);           // (16, 32)
    sgemm_kernel<<<gq, 256>>>(ROWS, INNER, DIM, xn, Wq, q);
    dim3 gkv(2 * INNER / GBN, ROWS / GBM);      // (32, 32)
    sgemm_kernel<<<gkv, 256>>>(ROWS, 2 * INNER, DIM, xn, Wkv, kv);

    // 3) RoPE on q and k (k = first half of kv columns)
    const size_t ropeN = (size_t)ROWS * HEADS * 64;
    const int ropeBlocks = (int)((ropeN + 255) / 256);
    rope_kernel<<<ropeBlocks, 256>>>(q,  re, INNER);
    rope_kernel<<<ropeBlocks, 256>>>(kv, re, 2 * INNER);

    // 4) causal attention
    dim3 ga(N_SEQ / AT_BM, B * HEADS);          // (32, 32)
    attn_kernel<<<ga, 256>>>(q, kv, o);

    // 5) output projection
    sgemm_kernel<<<gq, 256>>>(ROWS, INNER, DIM, o, Wo, out);
}

// round 2
// speedup vs baseline: 1.6316x; 1.6316x over previous
#include <cuda_runtime.h>
#include <cuda_bf16.h>
#include <math.h>
#include <stdint.h>

// ----------------------------------------------------------------------------
// Problem constants
// ----------------------------------------------------------------------------
#define B      2
#define N_SEQ  2048
#define DIM    2048
#define HEADS  16
#define DHEAD  128
#define INNER  (HEADS * DHEAD)       // 2048
#define ROWS   (B * N_SEQ)           // 4096

// ----------------------------------------------------------------------------
// Scratch (device globals; no allocations allowed)
// ----------------------------------------------------------------------------
__device__ float g_xn[ROWS * DIM];          // normalized input    [4096, 2048]
__device__ float g_q [ROWS * INNER];        // q projection        [4096, 2048]
__device__ float g_kv[ROWS * 2 * INNER];    // kv projection       [4096, 4096]
__device__ float g_o [ROWS * INNER];        // attention output    [4096, 2048]

// ----------------------------------------------------------------------------
// RMSNorm:  xn = x / max(rms(x), 1e-8) * g
// ----------------------------------------------------------------------------
__global__ __launch_bounds__(256) void rmsnorm_kernel(
    const float* __restrict__ x, const float* __restrict__ g,
    float* __restrict__ xn)
{
    const int row = blockIdx.x;
    const float* xr = x  + (size_t)row * DIM;
    float*       xo = xn + (size_t)row * DIM;

    float ss = 0.f;
    for (int i = threadIdx.x; i < DIM; i += 256) {
        float v = xr[i];
        ss += v * v;
    }
    __shared__ float red[8];
    #pragma unroll
    for (int o = 16; o > 0; o >>= 1) ss += __shfl_xor_sync(0xffffffffu, ss, o);
    if ((threadIdx.x & 31) == 0) red[threadIdx.x >> 5] = ss;
    __syncthreads();
    if (threadIdx.x < 8) {
        float v = red[threadIdx.x];
        #pragma unroll
        for (int o = 4; o > 0; o >>= 1) v += __shfl_xor_sync(0x000000ffu, v, o);
        if (threadIdx.x == 0) red[0] = v;
    }
    __syncthreads();
    const float rms = sqrtf(red[0] * (1.f / (float)DIM));
    const float inv = 1.f / fmaxf(rms, 1e-8f);
    for (int i = threadIdx.x; i < DIM; i += 256)
        xo[i] = xr[i] * inv * g[i];
}

// ----------------------------------------------------------------------------
// TF32 tensor-core GEMM: C[M,N] = A[M,K] @ B[K,N] (row-major, tiles divide)
// BM=128 BN=128 BK=16, 256 threads = 8 warps (4x2), warp tile 32x64.
// mma.sync.aligned.m16n8k8.row.col.f32.tf32.tf32.f32
// ----------------------------------------------------------------------------
__device__ __forceinline__ uint32_t f2tf32(float f) {
    uint32_t u;
    asm("cvt.rna.tf32.f32 %0, %1;" : "=r"(u) : "f"(f));
    return u;
}

__device__ __forceinline__ void mma_tf32(float* c, const uint32_t* a, const uint32_t* b) {
    asm volatile(
        "mma.sync.aligned.m16n8k8.row.col.f32.tf32.tf32.f32 "
        "{%0,%1,%2,%3},{%4,%5,%6,%7},{%8,%9},{%0,%1,%2,%3};"
        : "+f"(c[0]), "+f"(c[1]), "+f"(c[2]), "+f"(c[3])
        : "r"(a[0]), "r"(a[1]), "r"(a[2]), "r"(a[3]), "r"(b[0]), "r"(b[1]));
}

#define T_BM 128
#define T_BN 128
#define T_BK 16
#define AS_STRIDE 20    // pad 4: fragment gather hits all 32 banks
#define BS_STRIDE 136   // pad 8: fragment gather hits all 32 banks

__global__ __launch_bounds__(256, 2) void tf32_gemm_kernel(
    int M, int N, int K,
    const float* __restrict__ A, const float* __restrict__ Bm,
    float* __restrict__ C)
{
    __shared__ float As[T_BM][AS_STRIDE];
    __shared__ float Bs[T_BK][BS_STRIDE];

    const int tid  = threadIdx.x;
    const int lane = tid & 31;
    const int warp = tid >> 5;
    const int wm   = warp >> 1;          // 0..3
    const int wn   = warp & 1;           // 0..1
    const int mbase = wm * 32;
    const int nbase = wn * 64;

    // global loaders
    const int aRow = tid >> 2;           // 0..63 (and +64)
    const int aCol = (tid & 3) * 4;      // 0,4,8,12
    const int bRow = tid >> 5;           // 0..7 (and +8)
    const int bCol = (tid & 31) * 4;     // 0..124

    const float* Ap = A  + (size_t)blockIdx.y * T_BM * K;
    const float* Bp = Bm + (size_t)blockIdx.x * T_BN;

    float4 aReg[2], bReg[2];
    aReg[0] = *(const float4*)(Ap + (size_t)aRow        * K + aCol);
    aReg[1] = *(const float4*)(Ap + (size_t)(aRow + 64) * K + aCol);
    bReg[0] = *(const float4*)(Bp + (size_t)bRow        * N + bCol);
    bReg[1] = *(const float4*)(Bp + (size_t)(bRow + 8)  * N + bCol);

    float acc[2][8][4];
    #pragma unroll
    for (int mi = 0; mi < 2; mi++)
        #pragma unroll
        for (int ni = 0; ni < 8; ni++)
            #pragma unroll
            for (int e = 0; e < 4; e++) acc[mi][ni][e] = 0.f;

    for (int k0 = 0; k0 < K; k0 += T_BK) {
        // store staged regs to smem
        As[aRow     ][aCol + 0] = aReg[0].x;
        As[aRow     ][aCol + 1] = aReg[0].y;
        As[aRow     ][aCol + 2] = aReg[0].z;
        As[aRow     ][aCol + 3] = aReg[0].w;
        As[aRow + 64][aCol + 0] = aReg[1].x;
        As[aRow + 64][aCol + 1] = aReg[1].y;
        As[aRow + 64][aCol + 2] = aReg[1].z;
        As[aRow + 64][aCol + 3] = aReg[1].w;
        *(float4*)&Bs[bRow    ][bCol] = bReg[0];
        *(float4*)&Bs[bRow + 8][bCol] = bReg[1];
        __syncthreads();

        // prefetch next tile
        if (k0 + T_BK < K) {
            const float* Apn = Ap + (k0 + T_BK);
            const float* Bpn = Bp + (size_t)(k0 + T_BK) * N;
            aReg[0] = *(const float4*)(Apn + (size_t)aRow        * K + aCol);
            aReg[1] = *(const float4*)(Apn + (size_t)(aRow + 64) * K + aCol);
            bReg[0] = *(const float4*)(Bpn + (size_t)bRow        * N + bCol);
            bReg[1] = *(const float4*)(Bpn + (size_t)(bRow + 8)  * N + bCol);
        }

        // compute: two k=8 steps
        #pragma unroll
        for (int ks = 0; ks < T_BK; ks += 8) {
            uint32_t afrag[2][4];
            uint32_t bfrag[8][2];
            const int ar = mbase + (lane >> 2);
            const int ac = ks + (lane & 3);
            #pragma unroll
            for (int mi = 0; mi < 2; mi++) {
                afrag[mi][0] = f2tf32(As[ar + mi * 16    ][ac]);
                afrag[mi][1] = f2tf32(As[ar + mi * 16 + 8][ac]);
                afrag[mi][2] = f2tf32(As[ar + mi * 16    ][ac + 4]);
                afrag[mi][3] = f2tf32(As[ar + mi * 16 + 8][ac + 4]);
            }
            const int br = ks + (lane & 3);
            const int bc = nbase + (lane >> 2);
            #pragma unroll
            for (int ni = 0; ni < 8; ni++) {
                bfrag[ni][0] = f2tf32(Bs[br    ][bc + ni * 8]);
                bfrag[ni][1] = f2tf32(Bs[br + 4][bc + ni * 8]);
            }
            #pragma unroll
            for (int mi = 0; mi < 2; mi++)
                #pragma unroll
                for (int ni = 0; ni < 8; ni++)
                    mma_tf32(acc[mi][ni], afrag[mi], bfrag[ni]);
        }
        __syncthreads();
    }

    // epilogue
    float* Cp = C + (size_t)(blockIdx.y * T_BM + mbase) * N + blockIdx.x * T_BN + nbase;
    #pragma unroll
    for (int mi = 0; mi < 2; mi++) {
        const int r = mi * 16 + (lane >> 2);
        #pragma unroll
        for (int ni = 0; ni < 8; ni++) {
            const int c = ni * 8 + (lane & 3) * 2;
            *(float2*)(Cp + (size_t)r       * N + c) = make_float2(acc[mi][ni][0], acc[mi][ni][1]);
            *(float2*)(Cp + (size_t)(r + 8) * N + c) = make_float2(acc[mi][ni][2], acc[mi][ni][3]);
        }
    }
}

// ----------------------------------------------------------------------------
// RoPE (in place). Buffer is [ROWS, ncols]; heads live at col0 + h*DHEAD.
// ----------------------------------------------------------------------------
__global__ __launch_bounds__(256) void rope_kernel(
    float* __restrict__ t, const float* __restrict__ re, int ncols)
{
    const size_t total = (size_t)ROWS * HEADS * 64;
    size_t idx = (size_t)blockIdx.x * blockDim.x + threadIdx.x;
    if (idx >= total) return;
    const int d = (int)(idx & 63);
    const int h = (int)((idx >> 6) & (HEADS - 1));
    const int r = (int)(idx >> 10);
    const int n = r & (N_SEQ - 1);

    float* base = t + (size_t)r * ncols + h * DHEAD;
    const float p1 = re[n * DHEAD + d];
    const float p2 = re[n * DHEAD + d + 64];
    const float t1 = base[d];
    const float t2 = base[d + 64];
    base[d]      = t1 * cosf(p1) - t2 * sinf(p1);
    base[d + 64] = t2 * cosf(p2) + t1 * sinf(p2);
}

// ----------------------------------------------------------------------------
// Causal flash attention, fp32.
// ----------------------------------------------------------------------------
#define AT_BM 64
#define AT_BN 32

__global__ __launch_bounds__(256) void attn_kernel(
    const float* __restrict__ Q, const float* __restrict__ KV,
    float* __restrict__ O)
{
    const int bh = blockIdx.y;
    const int b  = bh >> 4;
    const int h  = bh & 15;
    const int qt = blockIdx.x;

    const int tid  = threadIdx.x;
    const int row  = tid >> 2;     // 0..63
    const int part = tid & 3;      // 0..3
    const int qrow = qt * AT_BM + row;

    __shared__ float Ks[AT_BN][DHEAD];
    __shared__ float Vs[AT_BN][DHEAD];

    const float* qptr = Q + ((size_t)(b * N_SEQ + qrow)) * INNER + h * DHEAD;
    float qreg[32];
    #pragma unroll
    for (int i = 0; i < 32; i++) qreg[i] = qptr[4 * i + part];

    float oacc[32] = {};
    float m = -INFINITY, l = 0.f;
    const float scale = 0.088388347648318447f;  // 128^-0.5
    const int lanebase = (tid & 31) & ~3;

    const int ntiles = 2 * qt + 2;
    for (int kt = 0; kt < ntiles; kt++) {
        __syncthreads();
        for (int idx = tid; idx < AT_BN * 32; idx += 256) {
            const int j  = idx >> 5;
            const int dd = (idx & 31) * 4;
            const size_t gro = ((size_t)(b * N_SEQ + kt * AT_BN + j)) * (2 * INNER);
            *(float4*)&Ks[j][dd] = *(const float4*)(KV + gro + h * DHEAD + dd);
            *(float4*)&Vs[j][dd] = *(const float4*)(KV + gro + INNER + h * DHEAD + dd);
        }
        __syncthreads();

        float pbuf[8];
        float tmax = -INFINITY;
        #pragma unroll 1
        for (int j = 0; j < AT_BN; j++) {
            float s = 0.f;
            #pragma unroll
            for (int i = 0; i < 32; i++) s += qreg[i] * Ks[j][4 * i + part];
            s += __shfl_xor_sync(0xffffffffu, s, 1);
            s += __shfl_xor_sync(0xffffffffu, s, 2);
            s *= scale;
            const int jg = kt * AT_BN + j;
            if (jg > qrow) s = -INFINITY;
            if ((j >> 3) == part) pbuf[j & 7] = s;
            tmax = fmaxf(tmax, s);
        }

        const float mnew = fmaxf(m, tmax);
        const float corr = __expf(m - mnew);
        l *= corr;
        #pragma unroll
        for (int i = 0; i < 32; i++) oacc[i] *= corr;
        float psum = 0.f;
        #pragma unroll
        for (int jj = 0; jj < 8; jj++) {
            pbuf[jj] = __expf(pbuf[jj] - mnew);
            psum += pbuf[jj];
        }
        psum += __shfl_xor_sync(0xffffffffu, psum, 1);
        psum += __shfl_xor_sync(0xffffffffu, psum, 2);
        l += psum;
        m = mnew;

        #pragma unroll 1
        for (int j = 0; j < AT_BN; j++) {
            const float p = __shfl_sync(0xffffffffu, pbuf[j & 7], lanebase + (j >> 3));
            #pragma unroll
            for (int i = 0; i < 32; i++) oacc[i] += p * Vs[j][4 * i + part];
        }
    }

    const float inv = 1.f / l;
    float* optr = O + ((size_t)(b * N_SEQ + qrow)) * INNER + h * DHEAD;
    #pragma unroll
    for (int i = 0; i < 32; i++) optr[4 * i + part] = oacc[i] * inv;
}

// ----------------------------------------------------------------------------
// Launch
// ----------------------------------------------------------------------------
extern "C" void kernel_launch(void* const* d_in, const int* in_sizes, int n_in,
                              void* d_out, int out_size)
{
    const float* x   = (const float*)d_in[0];
    const float* re  = (const float*)d_in[1];
    const float* g   = (const float*)d_in[2];
    const float* Wq  = (const float*)d_in[3];
    const float* Wkv = (const float*)d_in[4];
    const float* Wo  = (const float*)d_in[5];
    float* out = (float*)d_out;

    float *xn, *q, *kv, *o;
    cudaGetSymbolAddress((void**)&xn, g_xn);
    cudaGetSymbolAddress((void**)&q,  g_q);
    cudaGetSymbolAddress((void**)&kv, g_kv);
    cudaGetSymbolAddress((void**)&o,  g_o);

    // 1) RMSNorm
    rmsnorm_kernel<<<ROWS, 256>>>(x, g, xn);

    // 2) projections (tf32 tensor cores)
    dim3 gq(INNER / T_BN, ROWS / T_BM);           // (16, 32)
    tf32_gemm_kernel<<<gq, 256>>>(ROWS, INNER, DIM, xn, Wq, q);
    dim3 gkv(2 * INNER / T_BN, ROWS / T_BM);      // (32, 32)
    tf32_gemm_kernel<<<gkv, 256>>>(ROWS, 2 * INNER, DIM, xn, Wkv, kv);

    // 3) RoPE on q and k (k = first half of kv columns)
    const size_t ropeN = (size_t)ROWS * HEADS * 64;
    const int ropeBlocks = (int)((ropeN + 255) / 256);
    rope_kernel<<<ropeBlocks, 256>>>(q,  re, INNER);
    rope_kernel<<<ropeBlocks, 256>>>(kv, re, 2 * INNER);

    // 4) causal attention
    dim3 ga(N_SEQ / AT_BM, B * HEADS);            // (32, 32)
    attn_kernel<<<ga, 256>>>(q, kv, o);

    // 5) output projection (tf32 tensor cores)
    tf32_gemm_kernel<<<gq, 256>>>(ROWS, INNER, DIM, o, Wo, out);
}

// round 4
// speedup vs baseline: 4.1434x; 2.5394x over previous
#include <cuda_runtime.h>
#include <cuda_bf16.h>
#include <math.h>
#include <stdint.h>

// ----------------------------------------------------------------------------
// Problem constants
// ----------------------------------------------------------------------------
#define B      2
#define N_SEQ  2048
#define DIM    2048
#define HEADS  16
#define DHEAD  128
#define INNER  (HEADS * DHEAD)       // 2048
#define ROWS   (B * N_SEQ)           // 4096

// ----------------------------------------------------------------------------
// Scratch (device globals; no allocations allowed)
// ----------------------------------------------------------------------------
__device__ float g_xn[ROWS * DIM];
__device__ float g_q [ROWS * INNER];
__device__ float g_kv[ROWS * 2 * INNER];
__device__ float g_o [ROWS * INNER];

// ----------------------------------------------------------------------------
// tf32 helpers
// ----------------------------------------------------------------------------
__device__ __forceinline__ uint32_t f2tf32(float f) {
    uint32_t u;
    asm("cvt.rna.tf32.f32 %0, %1;" : "=r"(u) : "f"(f));
    return u;
}

__device__ __forceinline__ void mma_tf32(float* c, const uint32_t* a, const uint32_t* b) {
    asm volatile(
        "mma.sync.aligned.m16n8k8.row.col.f32.tf32.tf32.f32 "
        "{%0,%1,%2,%3},{%4,%5,%6,%7},{%8,%9},{%0,%1,%2,%3};"
        : "+f"(c[0]), "+f"(c[1]), "+f"(c[2]), "+f"(c[3])
        : "r"(a[0]), "r"(a[1]), "r"(a[2]), "r"(a[3]), "r"(b[0]), "r"(b[1]));
}

// ----------------------------------------------------------------------------
// RMSNorm
// ----------------------------------------------------------------------------
__global__ __launch_bounds__(256) void rmsnorm_kernel(
    const float* __restrict__ x, const float* __restrict__ g,
    float* __restrict__ xn)
{
    const int row = blockIdx.x;
    const float* xr = x  + (size_t)row * DIM;
    float*       xo = xn + (size_t)row * DIM;

    float ss = 0.f;
    for (int i = threadIdx.x; i < DIM; i += 256) {
        float v = xr[i];
        ss += v * v;
    }
    __shared__ float red[8];
    #pragma unroll
    for (int o = 16; o > 0; o >>= 1) ss += __shfl_xor_sync(0xffffffffu, ss, o);
    if ((threadIdx.x & 31) == 0) red[threadIdx.x >> 5] = ss;
    __syncthreads();
    if (threadIdx.x < 8) {
        float v = red[threadIdx.x];
        #pragma unroll
        for (int o = 4; o > 0; o >>= 1) v += __shfl_xor_sync(0x000000ffu, v, o);
        if (threadIdx.x == 0) red[0] = v;
    }
    __syncthreads();
    const float rms = sqrtf(red[0] * (1.f / (float)DIM));
    const float inv = 1.f / fmaxf(rms, 1e-8f);
    for (int i = threadIdx.x; i < DIM; i += 256)
        xo[i] = xr[i] * inv * g[i];
}

// ----------------------------------------------------------------------------
// TF32 tensor-core GEMM
// ----------------------------------------------------------------------------
#define T_BM 128
#define T_BN 128
#define T_BK 16
#define AS_STRIDE 20
#define BS_STRIDE 136

__global__ __launch_bounds__(256, 2) void tf32_gemm_kernel(
    int M, int N, int K,
    const float* __restrict__ A, const float* __restrict__ Bm,
    float* __restrict__ C)
{
    __shared__ float As[T_BM][AS_STRIDE];
    __shared__ float Bs[T_BK][BS_STRIDE];

    const int tid  = threadIdx.x;
    const int lane = tid & 31;
    const int warp = tid >> 5;
    const int wm   = warp >> 1;
    const int wn   = warp & 1;
    const int mbase = wm * 32;
    const int nbase = wn * 64;

    const int aRow = tid >> 2;
    const int aCol = (tid & 3) * 4;
    const int bRow = tid >> 5;
    const int bCol = (tid & 31) * 4;

    const float* Ap = A  + (size_t)blockIdx.y * T_BM * K;
    const float* Bp = Bm + (size_t)blockIdx.x * T_BN;

    float4 aReg[2], bReg[2];
    aReg[0] = *(const float4*)(Ap + (size_t)aRow        * K + aCol);
    aReg[1] = *(const float4*)(Ap + (size_t)(aRow + 64) * K + aCol);
    bReg[0] = *(const float4*)(Bp + (size_t)bRow        * N + bCol);
    bReg[1] = *(const float4*)(Bp + (size_t)(bRow + 8)  * N + bCol);

    float acc[2][8][4];
    #pragma unroll
    for (int mi = 0; mi < 2; mi++)
        #pragma unroll
        for (int ni = 0; ni < 8; ni++)
            #pragma unroll
            for (int e = 0; e < 4; e++) acc[mi][ni][e] = 0.f;

    for (int k0 = 0; k0 < K; k0 += T_BK) {
        As[aRow     ][aCol + 0] = aReg[0].x;
        As[aRow     ][aCol + 1] = aReg[0].y;
        As[aRow     ][aCol + 2] = aReg[0].z;
        As[aRow     ][aCol + 3] = aReg[0].w;
        As[aRow + 64][aCol + 0] = aReg[1].x;
        As[aRow + 64][aCol + 1] = aReg[1].y;
        As[aRow + 64][aCol + 2] = aReg[1].z;
        As[aRow + 64][aCol + 3] = aReg[1].w;
        *(float4*)&Bs[bRow    ][bCol] = bReg[0];
        *(float4*)&Bs[bRow + 8][bCol] = bReg[1];
        __syncthreads();

        if (k0 + T_BK < K) {
            const float* Apn = Ap + (k0 + T_BK);
            const float* Bpn = Bp + (size_t)(k0 + T_BK) * N;
            aReg[0] = *(const float4*)(Apn + (size_t)aRow        * K + aCol);
            aReg[1] = *(const float4*)(Apn + (size_t)(aRow + 64) * K + aCol);
            bReg[0] = *(const float4*)(Bpn + (size_t)bRow        * N + bCol);
            bReg[1] = *(const float4*)(Bpn + (size_t)(bRow + 8)  * N + bCol);
        }

        #pragma unroll
        for (int ks = 0; ks < T_BK; ks += 8) {
            uint32_t afrag[2][4];
            uint32_t bfrag[8][2];
            const int ar = mbase + (lane >> 2);
            const int ac = ks + (lane & 3);
            #pragma unroll
            for (int mi = 0; mi < 2; mi++) {
                afrag[mi][0] = f2tf32(As[ar + mi * 16    ][ac]);
                afrag[mi][1] = f2tf32(As[ar + mi * 16 + 8][ac]);
                afrag[mi][2] = f2tf32(As[ar + mi * 16    ][ac + 4]);
                afrag[mi][3] = f2tf32(As[ar + mi * 16 + 8][ac + 4]);
            }
            const int br = ks + (lane & 3);
            const int bc = nbase + (lane >> 2);
            #pragma unroll
            for (int ni = 0; ni < 8; ni++) {
                bfrag[ni][0] = f2tf32(Bs[br    ][bc + ni * 8]);
                bfrag[ni][1] = f2tf32(Bs[br + 4][bc + ni * 8]);
            }
            #pragma unroll
            for (int mi = 0; mi < 2; mi++)
                #pragma unroll
                for (int ni = 0; ni < 8; ni++)
                    mma_tf32(acc[mi][ni], afrag[mi], bfrag[ni]);
        }
        __syncthreads();
    }

    float* Cp = C + (size_t)(blockIdx.y * T_BM + mbase) * N + blockIdx.x * T_BN + nbase;
    #pragma unroll
    for (int mi = 0; mi < 2; mi++) {
        const int r = mi * 16 + (lane >> 2);
        #pragma unroll
        for (int ni = 0; ni < 8; ni++) {
            const int c = ni * 8 + (lane & 3) * 2;
            *(float2*)(Cp + (size_t)r       * N + c) = make_float2(acc[mi][ni][0], acc[mi][ni][1]);
            *(float2*)(Cp + (size_t)(r + 8) * N + c) = make_float2(acc[mi][ni][2], acc[mi][ni][3]);
        }
    }
}

// ----------------------------------------------------------------------------
// RoPE (in place)
// ----------------------------------------------------------------------------
__global__ __launch_bounds__(256) void rope_kernel(
    float* __restrict__ t, const float* __restrict__ re, int ncols)
{
    const size_t total = (size_t)ROWS * HEADS * 64;
    size_t idx = (size_t)blockIdx.x * blockDim.x + threadIdx.x;
    if (idx >= total) return;
    const int d = (int)(idx & 63);
    const int h = (int)((idx >> 6) & (HEADS - 1));
    const int r = (int)(idx >> 10);
    const int n = r & (N_SEQ - 1);

    float* base = t + (size_t)r * ncols + h * DHEAD;
    const float p1 = re[n * DHEAD + d];
    const float p2 = re[n * DHEAD + d + 64];
    const float t1 = base[d];
    const float t2 = base[d + 64];
    base[d]      = t1 * cosf(p1) - t2 * sinf(p1);
    base[d + 64] = t2 * cosf(p2) + t1 * sinf(p2);
}

// ----------------------------------------------------------------------------
// Causal flash attention on tf32 tensor cores.
//   grid = (N_SEQ/128, B*HEADS), 256 threads = 8 warps, warp owns 16 q rows.
//   Tiles: BM=128 queries x BN=64 keys. Q/K/V staged in smem as tf32 bits.
//   Smem stride 132 -> all fragment gathers conflict-free.
// ----------------------------------------------------------------------------
#define FA_BM 128
#define FA_BN 64
#define FA_STRIDE 132
#define FA_SMEM ((FA_BM + 2 * FA_BN) * FA_STRIDE * 4)

__global__ __launch_bounds__(256, 1) void attn_tc_kernel(
    const float* __restrict__ Q, const float* __restrict__ KV,
    float* __restrict__ O)
{
    extern __shared__ float sm[];
    float* Qs = sm;                          // [128][132] tf32 bits
    float* Ks = Qs + FA_BM * FA_STRIDE;      // [64][132]
    float* Vs = Ks + FA_BN * FA_STRIDE;      // [64][132]

    const int bh = blockIdx.y;
    const int b  = bh >> 4;
    const int h  = bh & 15;
    const int qt = blockIdx.x;

    const int tid  = threadIdx.x;
    const int lane = tid & 31;
    const int warp = tid >> 5;

    // load Q tile (convert to tf32 at store)
    const float* qbase = Q + ((size_t)(b * N_SEQ + qt * FA_BM)) * INNER + h * DHEAD;
    #pragma unroll
    for (int i = 0; i < 16; i++) {
        const int idx = i * 256 + tid;       // 0..4095
        const int r = idx >> 5;
        const int c = (idx & 31) * 4;
        float4 v = *(const float4*)(qbase + (size_t)r * INNER + c);
        uint4 u = make_uint4(f2tf32(v.x), f2tf32(v.y), f2tf32(v.z), f2tf32(v.w));
        *(uint4*)&Qs[r * FA_STRIDE + c] = u;
    }

    float oacc[16][4];
    #pragma unroll
    for (int nd = 0; nd < 16; nd++)
        #pragma unroll
        for (int e = 0; e < 4; e++) oacc[nd][e] = 0.f;

    float m0 = -INFINITY, m1 = -INFINITY, l0 = 0.f, l1 = 0.f;
    const int qrow0 = qt * FA_BM + warp * 16 + (lane >> 2);   // global row of c0/c1
    const int warp_max_row = qt * FA_BM + warp * 16 + 15;
    const float scale = 0.088388347648318447f;

    const int ntiles = 2 * qt + 2;
    for (int kt = 0; kt < ntiles; kt++) {
        __syncthreads();
        // load K,V tile (convert to tf32 at store)
        const float* kvbase = KV + ((size_t)(b * N_SEQ + kt * FA_BN)) * (2 * INNER) + h * DHEAD;
        #pragma unroll
        for (int i = 0; i < 8; i++) {
            const int idx = i * 256 + tid;   // 0..2047
            const int r = idx >> 5;
            const int c = (idx & 31) * 4;
            float4 kv4 = *(const float4*)(kvbase + (size_t)r * (2 * INNER) + c);
            float4 vv4 = *(const float4*)(kvbase + (size_t)r * (2 * INNER) + INNER + c);
            *(uint4*)&Ks[r * FA_STRIDE + c] =
                make_uint4(f2tf32(kv4.x), f2tf32(kv4.y), f2tf32(kv4.z), f2tf32(kv4.w));
            *(uint4*)&Vs[r * FA_STRIDE + c] =
                make_uint4(f2tf32(vv4.x), f2tf32(vv4.y), f2tf32(vv4.z), f2tf32(vv4.w));
        }
        __syncthreads();

        if (kt * FA_BN > warp_max_row) continue;   // tile fully above diagonal for this warp

        // ---- S = Q @ K^T -------------------------------------------------
        float sacc[8][4];
        #pragma unroll
        for (int ni = 0; ni < 8; ni++)
            #pragma unroll
            for (int e = 0; e < 4; e++) sacc[ni][e] = 0.f;

        #pragma unroll
        for (int ks = 0; ks < 16; ks++) {
            uint32_t a[4];
            const float* qp = &Qs[(warp * 16 + (lane >> 2)) * FA_STRIDE + ks * 8 + (lane & 3)];
            a[0] = __float_as_uint(qp[0]);
            a[1] = __float_as_uint(qp[8 * FA_STRIDE]);
            a[2] = __float_as_uint(qp[4]);
            a[3] = __float_as_uint(qp[8 * FA_STRIDE + 4]);
            #pragma unroll
            for (int ni = 0; ni < 8; ni++) {
                uint32_t bf[2];
                const float* kp = &Ks[(ni * 8 + (lane >> 2)) * FA_STRIDE + ks * 8 + (lane & 3)];
                bf[0] = __float_as_uint(kp[0]);
                bf[1] = __float_as_uint(kp[4]);
                mma_tf32(sacc[ni], a, bf);
            }
        }

        // ---- mask + online softmax --------------------------------------
        float rmax0 = -INFINITY, rmax1 = -INFINITY;
        #pragma unroll
        for (int ni = 0; ni < 8; ni++) {
            const int cg = kt * FA_BN + ni * 8 + 2 * (lane & 3);
            #pragma unroll
            for (int e = 0; e < 4; e++) {
                float s = sacc[ni][e] * scale;
                const int col = cg + (e & 1);
                const int row = qrow0 + (e >> 1) * 8;
                if (col > row) s = -INFINITY;
                sacc[ni][e] = s;
            }
            rmax0 = fmaxf(rmax0, fmaxf(sacc[ni][0], sacc[ni][1]));
            rmax1 = fmaxf(rmax1, fmaxf(sacc[ni][2], sacc[ni][3]));
        }
        rmax0 = fmaxf(rmax0, __shfl_xor_sync(0xffffffffu, rmax0, 1));
        rmax0 = fmaxf(rmax0, __shfl_xor_sync(0xffffffffu, rmax0, 2));
        rmax1 = fmaxf(rmax1, __shfl_xor_sync(0xffffffffu, rmax1, 1));
        rmax1 = fmaxf(rmax1, __shfl_xor_sync(0xffffffffu, rmax1, 2));

        const float mn0 = fmaxf(m0, rmax0);
        const float mn1 = fmaxf(m1, rmax1);
        const float c0 = __expf(m0 - mn0);
        const float c1 = __expf(m1 - mn1);
        float ps0 = 0.f, ps1 = 0.f;
        #pragma unroll
        for (int ni = 0; ni < 8; ni++) {
            sacc[ni][0] = __expf(sacc[ni][0] - mn0);
            sacc[ni][1] = __expf(sacc[ni][1] - mn0);
            sacc[ni][2] = __expf(sacc[ni][2] - mn1);
            sacc[ni][3] = __expf(sacc[ni][3] - mn1);
            ps0 += sacc[ni][0] + sacc[ni][1];
            ps1 += sacc[ni][2] + sacc[ni][3];
        }
        ps0 += __shfl_xor_sync(0xffffffffu, ps0, 1);
        ps0 += __shfl_xor_sync(0xffffffffu, ps0, 2);
        ps1 += __shfl_xor_sync(0xffffffffu, ps1, 1);
        ps1 += __shfl_xor_sync(0xffffffffu, ps1, 2);
        l0 = l0 * c0 + ps0;
        l1 = l1 * c1 + ps1;
        m0 = mn0;
        m1 = mn1;
        #pragma unroll
        for (int nd = 0; nd < 16; nd++) {
            oacc[nd][0] *= c0;
            oacc[nd][1] *= c0;
            oacc[nd][2] *= c1;
            oacc[nd][3] *= c1;
        }

        // ---- O += P @ V  (shuffle-transpose P acc -> A frag) ------------
        #pragma unroll
        for (int jc = 0; jc < 8; jc++) {
            const int src0 = (lane & ~3) | ((lane & 3) >> 1);
            const int src1 = src0 + 2;
            const float g00 = __shfl_sync(0xffffffffu, sacc[jc][0], src0);
            const float g01 = __shfl_sync(0xffffffffu, sacc[jc][1], src0);
            const float g10 = __shfl_sync(0xffffffffu, sacc[jc][0], src1);
            const float g11 = __shfl_sync(0xffffffffu, sacc[jc][1], src1);
            const float g20 = __shfl_sync(0xffffffffu, sacc[jc][2], src0);
            const float g21 = __shfl_sync(0xffffffffu, sacc[jc][3], src0);
            const float g30 = __shfl_sync(0xffffffffu, sacc[jc][2], src1);
            const float g31 = __shfl_sync(0xffffffffu, sacc[jc][3], src1);
            const bool odd = lane & 1;
            uint32_t a[4];
            a[0] = f2tf32(odd ? g01 : g00);   // P[r0][k]
            a[1] = f2tf32(odd ? g21 : g20);   // P[r1][k]
            a[2] = f2tf32(odd ? g11 : g10);   // P[r0][k+4]
            a[3] = f2tf32(odd ? g31 : g30);   // P[r1][k+4]
            #pragma unroll
            for (int nd = 0; nd < 16; nd++) {
                uint32_t bf[2];
                const float* vp = &Vs[(jc * 8 + (lane & 3)) * FA_STRIDE + nd * 8 + (lane >> 2)];
                bf[0] = __float_as_uint(vp[0]);
                bf[1] = __float_as_uint(vp[4 * FA_STRIDE]);
                mma_tf32(oacc[nd], a, bf);
            }
        }
    }

    // epilogue
    const float inv0 = 1.f / l0;
    const float inv1 = 1.f / l1;
    float* ob = O + ((size_t)(b * N_SEQ + qt * FA_BM + warp * 16 + (lane >> 2))) * INNER
                  + h * DHEAD + 2 * (lane & 3);
    #pragma unroll
    for (int nd = 0; nd < 16; nd++) {
        *(float2*)(ob + nd * 8) = make_float2(oacc[nd][0] * inv0, oacc[nd][1] * inv0);
        *(float2*)(ob + (size_t)8 * INNER + nd * 8) =
            make_float2(oacc[nd][2] * inv1, oacc[nd][3] * inv1);
    }
}

// ----------------------------------------------------------------------------
// Launch
// ----------------------------------------------------------------------------
extern "C" void kernel_launch(void* const* d_in, const int* in_sizes, int n_in,
                              void* d_out, int out_size)
{
    const float* x   = (const float*)d_in[0];
    const float* re  = (const float*)d_in[1];
    const float* g   = (const float*)d_in[2];
    const float* Wq  = (const float*)d_in[3];
    const float* Wkv = (const float*)d_in[4];
    const float* Wo  = (const float*)d_in[5];
    float* out = (float*)d_out;

    float *xn, *q, *kv, *o;
    cudaGetSymbolAddress((void**)&xn, g_xn);
    cudaGetSymbolAddress((void**)&q,  g_q);
    cudaGetSymbolAddress((void**)&kv, g_kv);
    cudaGetSymbolAddress((void**)&o,  g_o);

    // 1) RMSNorm
    rmsnorm_kernel<<<ROWS, 256>>>(x, g, xn);

    // 2) projections (tf32 tensor cores)
    dim3 gq(INNER / T_BN, ROWS / T_BM);
    tf32_gemm_kernel<<<gq, 256>>>(ROWS, INNER, DIM, xn, Wq, q);
    dim3 gkv(2 * INNER / T_BN, ROWS / T_BM);
    tf32_gemm_kernel<<<gkv, 256>>>(ROWS, 2 * INNER, DIM, xn, Wkv, kv);

    // 3) RoPE on q and k
    const size_t ropeN = (size_t)ROWS * HEADS * 64;
    const int ropeBlocks = (int)((ropeN + 255) / 256);
    rope_kernel<<<ropeBlocks, 256>>>(q,  re, INNER);
    rope_kernel<<<ropeBlocks, 256>>>(kv, re, 2 * INNER);

    // 4) causal attention (tf32 tensor cores)
    cudaFuncSetAttribute(attn_tc_kernel,
                         cudaFuncAttributeMaxDynamicSharedMemorySize, FA_SMEM);
    dim3 ga(N_SEQ / FA_BM, B * HEADS);
    attn_tc_kernel<<<ga, 256, FA_SMEM>>>(q, kv, o);

    // 5) output projection (tf32 tensor cores)
    tf32_gemm_kernel<<<gq, 256>>>(ROWS, INNER, DIM, o, Wo, out);
}

// round 5
// speedup vs baseline: 4.2419x; 1.0238x over previous
#include <cuda_runtime.h>
#include <cuda_bf16.h>
#include <math.h>
#include <stdint.h>

// ----------------------------------------------------------------------------
// Problem constants
// ----------------------------------------------------------------------------
#define B      2
#define N_SEQ  2048
#define DIM    2048
#define HEADS  16
#define DHEAD  128
#define INNER  (HEADS * DHEAD)       // 2048
#define ROWS   (B * N_SEQ)           // 4096

// ----------------------------------------------------------------------------
// Scratch (device globals; no allocations allowed)
// ----------------------------------------------------------------------------
__device__ float g_xn[ROWS * DIM];
__device__ float g_q [ROWS * INNER];
__device__ float g_kv[ROWS * 2 * INNER];
__device__ float g_o [ROWS * INNER];

// ----------------------------------------------------------------------------
// tf32 helpers
// ----------------------------------------------------------------------------
__device__ __forceinline__ uint32_t f2tf32(float f) {
    uint32_t u;
    asm("cvt.rna.tf32.f32 %0, %1;" : "=r"(u) : "f"(f));
    return u;
}

__device__ __forceinline__ void mma_tf32(float* c, const uint32_t* a, const uint32_t* b) {
    asm volatile(
        "mma.sync.aligned.m16n8k8.row.col.f32.tf32.tf32.f32 "
        "{%0,%1,%2,%3},{%4,%5,%6,%7},{%8,%9},{%0,%1,%2,%3};"
        : "+f"(c[0]), "+f"(c[1]), "+f"(c[2]), "+f"(c[3])
        : "r"(a[0]), "r"(a[1]), "r"(a[2]), "r"(a[3]), "r"(b[0]), "r"(b[1]));
}

// ----------------------------------------------------------------------------
// RMSNorm
// ----------------------------------------------------------------------------
__global__ __launch_bounds__(256) void rmsnorm_kernel(
    const float* __restrict__ x, const float* __restrict__ g,
    float* __restrict__ xn)
{
    const int row = blockIdx.x;
    const float* xr = x  + (size_t)row * DIM;
    float*       xo = xn + (size_t)row * DIM;

    float ss = 0.f;
    for (int i = threadIdx.x; i < DIM; i += 256) {
        float v = xr[i];
        ss += v * v;
    }
    __shared__ float red[8];
    #pragma unroll
    for (int o = 16; o > 0; o >>= 1) ss += __shfl_xor_sync(0xffffffffu, ss, o);
    if ((threadIdx.x & 31) == 0) red[threadIdx.x >> 5] = ss;
    __syncthreads();
    if (threadIdx.x < 8) {
        float v = red[threadIdx.x];
        #pragma unroll
        for (int o = 4; o > 0; o >>= 1) v += __shfl_xor_sync(0x000000ffu, v, o);
        if (threadIdx.x == 0) red[0] = v;
    }
    __syncthreads();
    const float rms = sqrtf(red[0] * (1.f / (float)DIM));
    const float inv = 1.f / fmaxf(rms, 1e-8f);
    for (int i = threadIdx.x; i < DIM; i += 256)
        xo[i] = xr[i] * inv * g[i];
}

// ----------------------------------------------------------------------------
// TF32 tensor-core GEMM, double-buffered smem, tf32 conversion at smem store.
// ----------------------------------------------------------------------------
#define T_BM 128
#define T_BN 128
#define T_BK 16
#define AS_STRIDE 20
#define BS_STRIDE 136

__global__ __launch_bounds__(256, 2) void tf32_gemm_kernel(
    int M, int N, int K,
    const float* __restrict__ A, const float* __restrict__ Bm,
    float* __restrict__ C)
{
    __shared__ float As[2][T_BM][AS_STRIDE];
    __shared__ float Bs[2][T_BK][BS_STRIDE];

    const int tid  = threadIdx.x;
    const int lane = tid & 31;
    const int warp = tid >> 5;
    const int wm   = warp >> 1;
    const int wn   = warp & 1;
    const int mbase = wm * 32;
    const int nbase = wn * 64;

    const int aRow = tid >> 2;
    const int aCol = (tid & 3) * 4;
    const int bRow = tid >> 5;
    const int bCol = (tid & 31) * 4;

    const float* Ap = A  + (size_t)blockIdx.y * T_BM * K;
    const float* Bp = Bm + (size_t)blockIdx.x * T_BN;

    float4 aReg[2], bReg[2];
    aReg[0] = *(const float4*)(Ap + (size_t)aRow        * K + aCol);
    aReg[1] = *(const float4*)(Ap + (size_t)(aRow + 64) * K + aCol);
    bReg[0] = *(const float4*)(Bp + (size_t)bRow        * N + bCol);
    bReg[1] = *(const float4*)(Bp + (size_t)(bRow + 8)  * N + bCol);

    // store tile 0 (convert to tf32 bits at store)
    *(uint4*)&As[0][aRow     ][aCol] =
        make_uint4(f2tf32(aReg[0].x), f2tf32(aReg[0].y), f2tf32(aReg[0].z), f2tf32(aReg[0].w));
    *(uint4*)&As[0][aRow + 64][aCol] =
        make_uint4(f2tf32(aReg[1].x), f2tf32(aReg[1].y), f2tf32(aReg[1].z), f2tf32(aReg[1].w));
    *(uint4*)&Bs[0][bRow    ][bCol] =
        make_uint4(f2tf32(bReg[0].x), f2tf32(bReg[0].y), f2tf32(bReg[0].z), f2tf32(bReg[0].w));
    *(uint4*)&Bs[0][bRow + 8][bCol] =
        make_uint4(f2tf32(bReg[1].x), f2tf32(bReg[1].y), f2tf32(bReg[1].z), f2tf32(bReg[1].w));
    __syncthreads();

    float acc[2][8][4];
    #pragma unroll
    for (int mi = 0; mi < 2; mi++)
        #pragma unroll
        for (int ni = 0; ni < 8; ni++)
            #pragma unroll
            for (int e = 0; e < 4; e++) acc[mi][ni][e] = 0.f;

    const int nT = K / T_BK;
    for (int t = 0; t < nT; t++) {
        const int cur = t & 1;

        if (t + 1 < nT) {
            const float* Apn = Ap + (size_t)(t + 1) * T_BK;
            const float* Bpn = Bp + (size_t)(t + 1) * T_BK * N;
            aReg[0] = *(const float4*)(Apn + (size_t)aRow        * K + aCol);
            aReg[1] = *(const float4*)(Apn + (size_t)(aRow + 64) * K + aCol);
            bReg[0] = *(const float4*)(Bpn + (size_t)bRow        * N + bCol);
            bReg[1] = *(const float4*)(Bpn + (size_t)(bRow + 8)  * N + bCol);
        }

        #pragma unroll
        for (int ks = 0; ks < T_BK; ks += 8) {
            uint32_t afrag[2][4];
            uint32_t bfrag[8][2];
            const int ar = mbase + (lane >> 2);
            const int ac = ks + (lane & 3);
            #pragma unroll
            for (int mi = 0; mi < 2; mi++) {
                afrag[mi][0] = __float_as_uint(As[cur][ar + mi * 16    ][ac]);
                afrag[mi][1] = __float_as_uint(As[cur][ar + mi * 16 + 8][ac]);
                afrag[mi][2] = __float_as_uint(As[cur][ar + mi * 16    ][ac + 4]);
                afrag[mi][3] = __float_as_uint(As[cur][ar + mi * 16 + 8][ac + 4]);
            }
            const int br = ks + (lane & 3);
            const int bc = nbase + (lane >> 2);
            #pragma unroll
            for (int ni = 0; ni < 8; ni++) {
                bfrag[ni][0] = __float_as_uint(Bs[cur][br    ][bc + ni * 8]);
                bfrag[ni][1] = __float_as_uint(Bs[cur][br + 4][bc + ni * 8]);
            }
            #pragma unroll
            for (int mi = 0; mi < 2; mi++)
                #pragma unroll
                for (int ni = 0; ni < 8; ni++)
                    mma_tf32(acc[mi][ni], afrag[mi], bfrag[ni]);
        }

        if (t + 1 < nT) {
            const int nxt = cur ^ 1;
            *(uint4*)&As[nxt][aRow     ][aCol] =
                make_uint4(f2tf32(aReg[0].x), f2tf32(aReg[0].y), f2tf32(aReg[0].z), f2tf32(aReg[0].w));
            *(uint4*)&As[nxt][aRow + 64][aCol] =
                make_uint4(f2tf32(aReg[1].x), f2tf32(aReg[1].y), f2tf32(aReg[1].z), f2tf32(aReg[1].w));
            *(uint4*)&Bs[nxt][bRow    ][bCol] =
                make_uint4(f2tf32(bReg[0].x), f2tf32(bReg[0].y), f2tf32(bReg[0].z), f2tf32(bReg[0].w));
            *(uint4*)&Bs[nxt][bRow + 8][bCol] =
                make_uint4(f2tf32(bReg[1].x), f2tf32(bReg[1].y), f2tf32(bReg[1].z), f2tf32(bReg[1].w));
        }
        __syncthreads();
    }

    float* Cp = C + (size_t)(blockIdx.y * T_BM + mbase) * N + blockIdx.x * T_BN + nbase;
    #pragma unroll
    for (int mi = 0; mi < 2; mi++) {
        const int r = mi * 16 + (lane >> 2);
        #pragma unroll
        for (int ni = 0; ni < 8; ni++) {
            const int c = ni * 8 + (lane & 3) * 2;
            *(float2*)(Cp + (size_t)r       * N + c) = make_float2(acc[mi][ni][0], acc[mi][ni][1]);
            *(float2*)(Cp + (size_t)(r + 8) * N + c) = make_float2(acc[mi][ni][2], acc[mi][ni][3]);
        }
    }
}

// ----------------------------------------------------------------------------
// RoPE (in place), q and kv handled in one launch.
// ----------------------------------------------------------------------------
__global__ __launch_bounds__(256) void rope2_kernel(
    float* __restrict__ qb, float* __restrict__ kvb, const float* __restrict__ re)
{
    const size_t half = (size_t)ROWS * HEADS * 64;
    size_t idx = (size_t)blockIdx.x * blockDim.x + threadIdx.x;
    float* t;
    int ncols;
    if (idx >= half) {
        if (idx >= 2 * half) return;
        t = kvb; ncols = 2 * INNER; idx -= half;
    } else {
        t = qb; ncols = INNER;
    }
    const int d = (int)(idx & 63);
    const int h = (int)((idx >> 6) & (HEADS - 1));
    const int r = (int)(idx >> 10);
    const int n = r & (N_SEQ - 1);

    float* base = t + (size_t)r * ncols + h * DHEAD;
    const float p1 = re[n * DHEAD + d];
    const float p2 = re[n * DHEAD + d + 64];
    const float t1 = base[d];
    const float t2 = base[d + 64];
    base[d]      = t1 * cosf(p1) - t2 * sinf(p1);
    base[d + 64] = t2 * cosf(p2) + t1 * sinf(p2);
}

// ----------------------------------------------------------------------------
// Causal flash attention on tf32 tensor cores.
//   Register-resident Q fragments (scaled by 128^-0.5 * log2(e), tf32).
//   Smem: K,V tiles only. exp2-domain online softmax. Mask only diagonal tiles.
// ----------------------------------------------------------------------------
#define FA_BM 128
#define FA_BN 64
#define FA_STRIDE 132
#define FA_SMEM (2 * FA_BN * FA_STRIDE * 4)

__global__ __launch_bounds__(256, 1) void attn_tc_kernel(
    const float* __restrict__ Q, const float* __restrict__ KV,
    float* __restrict__ O)
{
    extern __shared__ float sm[];
    float* Ks = sm;                          // [64][132] tf32 bits
    float* Vs = sm + FA_BN * FA_STRIDE;      // [64][132]

    const int bh = blockIdx.y;
    const int b  = bh >> 4;
    const int h  = bh & 15;
    const int qt = blockIdx.x;

    const int tid  = threadIdx.x;
    const int lane = tid & 31;
    const int warp = tid >> 5;

    // Q fragments in registers, prescaled by scale*log2(e), tf32-rounded.
    const float qscale = 0.088388347648318447f * 1.4426950408889634f;
    uint32_t qfrag[16][4];
    {
        const float* qb = Q + ((size_t)(b * N_SEQ + qt * FA_BM + warp * 16 + (lane >> 2))) * INNER
                            + h * DHEAD + (lane & 3);
        #pragma unroll
        for (int ks = 0; ks < 16; ks++) {
            qfrag[ks][0] = f2tf32(qb[ks * 8]                 * qscale);
            qfrag[ks][1] = f2tf32(qb[8 * INNER + ks * 8]     * qscale);
            qfrag[ks][2] = f2tf32(qb[ks * 8 + 4]             * qscale);
            qfrag[ks][3] = f2tf32(qb[8 * INNER + ks * 8 + 4] * qscale);
        }
    }

    float oacc[16][4];
    #pragma unroll
    for (int nd = 0; nd < 16; nd++)
        #pragma unroll
        for (int e = 0; e < 4; e++) oacc[nd][e] = 0.f;

    float m0 = -INFINITY, m1 = -INFINITY, l0 = 0.f, l1 = 0.f;
    const int qrow0 = qt * FA_BM + warp * 16 + (lane >> 2);
    const int warp_min_row = qt * FA_BM + warp * 16;
    const int warp_max_row = warp_min_row + 15;

    const int ntiles = 2 * qt + 2;
    for (int kt = 0; kt < ntiles; kt++) {
        __syncthreads();
        const float* kvbase = KV + ((size_t)(b * N_SEQ + kt * FA_BN)) * (2 * INNER) + h * DHEAD;
        #pragma unroll
        for (int i = 0; i < 8; i++) {
            const int idx = i * 256 + tid;   // 0..2047
            const int r = idx >> 5;
            const int c = (idx & 31) * 4;
            float4 kv4 = *(const float4*)(kvbase + (size_t)r * (2 * INNER) + c);
            float4 vv4 = *(const float4*)(kvbase + (size_t)r * (2 * INNER) + INNER + c);
            *(uint4*)&Ks[r * FA_STRIDE + c] =
                make_uint4(f2tf32(kv4.x), f2tf32(kv4.y), f2tf32(kv4.z), f2tf32(kv4.w));
            *(uint4*)&Vs[r * FA_STRIDE + c] =
                make_uint4(f2tf32(vv4.x), f2tf32(vv4.y), f2tf32(vv4.z), f2tf32(vv4.w));
        }
        __syncthreads();

        if (kt * FA_BN > warp_max_row) continue;   // fully above diagonal for this warp

        // ---- S = Q @ K^T (log2-domain, prescaled) ------------------------
        float sacc[8][4];
        #pragma unroll
        for (int ni = 0; ni < 8; ni++)
            #pragma unroll
            for (int e = 0; e < 4; e++) sacc[ni][e] = 0.f;

        #pragma unroll
        for (int ks = 0; ks < 16; ks++) {
            #pragma unroll
            for (int ni = 0; ni < 8; ni++) {
                uint32_t bf[2];
                const float* kp = &Ks[(ni * 8 + (lane >> 2)) * FA_STRIDE + ks * 8 + (lane & 3)];
                bf[0] = __float_as_uint(kp[0]);
                bf[1] = __float_as_uint(kp[4]);
                mma_tf32(sacc[ni], qfrag[ks], bf);
            }
        }

        // ---- causal mask (diagonal tiles only) ---------------------------
        if (kt * FA_BN + FA_BN - 1 > warp_min_row) {
            #pragma unroll
            for (int ni = 0; ni < 8; ni++) {
                const int cg = kt * FA_BN + ni * 8 + 2 * (lane & 3);
                #pragma unroll
                for (int e = 0; e < 4; e++) {
                    const int col = cg + (e & 1);
                    const int row = qrow0 + (e >> 1) * 8;
                    if (col > row) sacc[ni][e] = -INFINITY;
                }
            }
        }

        // ---- online softmax (exp2 domain) --------------------------------
        float rmax0 = -INFINITY, rmax1 = -INFINITY;
        #pragma unroll
        for (int ni = 0; ni < 8; ni++) {
            rmax0 = fmaxf(rmax0, fmaxf(sacc[ni][0], sacc[ni][1]));
            rmax1 = fmaxf(rmax1, fmaxf(sacc[ni][2], sacc[ni][3]));
        }
        rmax0 = fmaxf(rmax0, __shfl_xor_sync(0xffffffffu, rmax0, 1));
        rmax0 = fmaxf(rmax0, __shfl_xor_sync(0xffffffffu, rmax0, 2));
        rmax1 = fmaxf(rmax1, __shfl_xor_sync(0xffffffffu, rmax1, 1));
        rmax1 = fmaxf(rmax1, __shfl_xor_sync(0xffffffffu, rmax1, 2));

        const float mn0 = fmaxf(m0, rmax0);
        const float mn1 = fmaxf(m1, rmax1);
        const float c0 = exp2f(m0 - mn0);
        const float c1 = exp2f(m1 - mn1);
        float ps0 = 0.f, ps1 = 0.f;
        #pragma unroll
        for (int ni = 0; ni < 8; ni++) {
            sacc[ni][0] = exp2f(sacc[ni][0] - mn0);
            sacc[ni][1] = exp2f(sacc[ni][1] - mn0);
            sacc[ni][2] = exp2f(sacc[ni][2] - mn1);
            sacc[ni][3] = exp2f(sacc[ni][3] - mn1);
            ps0 += sacc[ni][0] + sacc[ni][1];
            ps1 += sacc[ni][2] + sacc[ni][3];
        }
        ps0 += __shfl_xor_sync(0xffffffffu, ps0, 1);
        ps0 += __shfl_xor_sync(0xffffffffu, ps0, 2);
        ps1 += __shfl_xor_sync(0xffffffffu, ps1, 1);
        ps1 += __shfl_xor_sync(0xffffffffu, ps1, 2);
        l0 = l0 * c0 + ps0;
        l1 = l1 * c1 + ps1;
        m0 = mn0;
        m1 = mn1;
        #pragma unroll
        for (int nd = 0; nd < 16; nd++) {
            oacc[nd][0] *= c0;
            oacc[nd][1] *= c0;
            oacc[nd][2] *= c1;
            oacc[nd][3] *= c1;
        }

        // ---- O += P @ V  (shuffle-transpose P acc -> A frag) -------------
        #pragma unroll
        for (int jc = 0; jc < 8; jc++) {
            const int src0 = (lane & ~3) | ((lane & 3) >> 1);
            const int src1 = src0 + 2;
            const float g00 = __shfl_sync(0xffffffffu, sacc[jc][0], src0);
            const float g01 = __shfl_sync(0xffffffffu, sacc[jc][1], src0);
            const float g10 = __shfl_sync(0xffffffffu, sacc[jc][0], src1);
            const float g11 = __shfl_sync(0xffffffffu, sacc[jc][1], src1);
            const float g20 = __shfl_sync(0xffffffffu, sacc[jc][2], src0);
            const float g21 = __shfl_sync(0xffffffffu, sacc[jc][3], src0);
            const float g30 = __shfl_sync(0xffffffffu, sacc[jc][2], src1);
            const float g31 = __shfl_sync(0xffffffffu, sacc[jc][3], src1);
            const bool odd = lane & 1;
            uint32_t a[4];
            a[0] = f2tf32(odd ? g01 : g00);
            a[1] = f2tf32(odd ? g21 : g20);
            a[2] = f2tf32(odd ? g11 : g10);
            a[3] = f2tf32(odd ? g31 : g30);
            #pragma unroll
            for (int nd = 0; nd < 16; nd++) {
                uint32_t bf[2];
                const float* vp = &Vs[(jc * 8 + (lane & 3)) * FA_STRIDE + nd * 8 + (lane >> 2)];
                bf[0] = __float_as_uint(vp[0]);
                bf[1] = __float_as_uint(vp[4 * FA_STRIDE]);
                mma_tf32(oacc[nd], a, bf);
            }
        }
    }

    // epilogue
    const float inv0 = 1.f / l0;
    const float inv1 = 1.f / l1;
    float* ob = O + ((size_t)(b * N_SEQ + qt * FA_BM + warp * 16 + (lane >> 2))) * INNER
                  + h * DHEAD + 2 * (lane & 3);
    #pragma unroll
    for (int nd = 0; nd < 16; nd++) {
        *(float2*)(ob + nd * 8) = make_float2(oacc[nd][0] * inv0, oacc[nd][1] * inv0);
        *(float2*)(ob + (size_t)8 * INNER + nd * 8) =
            make_float2(oacc[nd][2] * inv1, oacc[nd][3] * inv1);
    }
}

// ----------------------------------------------------------------------------
// Launch
// ----------------------------------------------------------------------------
extern "C" void kernel_launch(void* const* d_in, const int* in_sizes, int n_in,
                              void* d_out, int out_size)
{
    const float* x   = (const float*)d_in[0];
    const float* re  = (const float*)d_in[1];
    const float* g   = (const float*)d_in[2];
    const float* Wq  = (const float*)d_in[3];
    const float* Wkv = (const float*)d_in[4];
    const float* Wo  = (const float*)d_in[5];
    float* out = (float*)d_out;

    float *xn, *q, *kv, *o;
    cudaGetSymbolAddress((void**)&xn, g_xn);
    cudaGetSymbolAddress((void**)&q,  g_q);
    cudaGetSymbolAddress((void**)&kv, g_kv);
    cudaGetSymbolAddress((void**)&o,  g_o);

    // 1) RMSNorm
    rmsnorm_kernel<<<ROWS, 256>>>(x, g, xn);

    // 2) projections (tf32 tensor cores)
    dim3 gq(INNER / T_BN, ROWS / T_BM);
    tf32_gemm_kernel<<<gq, 256>>>(ROWS, INNER, DIM, xn, Wq, q);
    dim3 gkv(2 * INNER / T_BN, ROWS / T_BM);
    tf32_gemm_kernel<<<gkv, 256>>>(ROWS, 2 * INNER, DIM, xn, Wkv, kv);

    // 3) RoPE on q and k (one launch)
    const size_t ropeN = 2 * (size_t)ROWS * HEADS * 64;
    const int ropeBlocks = (int)((ropeN + 255) / 256);
    rope2_kernel<<<ropeBlocks, 256>>>(q, kv, re);

    // 4) causal attention (tf32 tensor cores, reg-resident Q)
    cudaFuncSetAttribute(attn_tc_kernel,
                         cudaFuncAttributeMaxDynamicSharedMemorySize, FA_SMEM);
    dim3 ga(N_SEQ / FA_BM, B * HEADS);
    attn_tc_kernel<<<ga, 256, FA_SMEM>>>(q, kv, o);

    // 5) output projection (tf32 tensor cores)
    tf32_gemm_kernel<<<gq, 256>>>(ROWS, INNER, DIM, o, Wo, out);
}